// round 8
// baseline (speedup 1.0000x reference)
#include <cuda_runtime.h>
#include <cuda_bf16.h>
#include <cuda_fp16.h>
#include <cstdint>

#define NPTS 12288
#define DIM 16
#define KSPLIT 6
#define QT_TILES 96                     // 12288/128 query tiles
#define TPB 256
#define KEYS_PER_SPLIT (NPTS / KSPLIT)  // 2048
#define KEYTILE 512
#define TILES (KEYS_PER_SPLIT / KEYTILE)// 4
#define SOP_BLK 256
#define SOP_BLOCKS (NPTS / SOP_BLK)     // 48
#define BIAS 9.0f                       // d = score*log2(e) - BIAS (fp16 range fix)

// ---- scratch (__device__ globals; no allocation allowed) ------------------
__device__ uint32_t g_qa[NPTS * 8];         // queries, bf16x2, pre-scaled by 0.25*log2(e)
__device__ uint32_t g_kb[NPTS * 8];         // keys, bf16x2, unscaled
__device__ float g_se[KSPLIT][NPTS];        // exp-sum partials (2^-BIAS units)
__device__ float g_sw[KSPLIT][NPTS];        // exp*d-sum partials
__device__ float g_Mpart[SOP_BLOCKS][256];  // per-block SOP partials
__device__ unsigned int g_cnt = 0;          // last-block counter (self-resetting)

// ---------------------------------------------------------------------------
// Kernel 0: convert feats (f32) to bf16 row-major arrays.
// g_qa = feats * 0.25*log2(e)  (A operand; MMA output is score in log2 units)
// g_kb = feats                 (B operand)
// ---------------------------------------------------------------------------
__global__ void convert_kernel(const float* __restrict__ feats) {
    const int p = blockIdx.x * 256 + threadIdx.x;
    const float* f = feats + p * DIM;
    const float sc = 0.25f * 1.4426950408889634f;
    #pragma unroll
    for (int i = 0; i < 8; i++) {
        float x0 = f[2 * i], x1 = f[2 * i + 1];
        __nv_bfloat162 qa = __floats2bfloat162_rn(x0 * sc, x1 * sc);
        __nv_bfloat162 kb = __floats2bfloat162_rn(x0, x1);
        g_qa[p * 8 + i] = *reinterpret_cast<uint32_t*>(&qa);
        g_kb[p * 8 + i] = *reinterpret_cast<uint32_t*>(&kb);
    }
}

// ---------------------------------------------------------------------------
// Kernel 1: tensor-core attention row stats via warp-level mma.sync.
// Warp owns 16 queries (A frag); loops 512-key smem tiles (48B stride,
// conflict-free). MMA accumulator init = -BIAS so d = t - BIAS with
// t = score*log2(e). Epilogue in fp16x2: pack d pairs (F2FP), one
// ex2.approx.f16x2 per pair (2 exps / MUFU op), HADD2/HFMA2 accumulate,
// flush to fp32 every 8 MMAs. Identity: <ctx,f> = 4*ln2*(sw/se + BIAS).
// ---------------------------------------------------------------------------
__global__ void __launch_bounds__(TPB, 4) attn_mma_kernel() {
    __shared__ uint32_t sk[KEYTILE * 12];   // 24 KB, 48B per key (12 words)

    const int tid  = threadIdx.x;
    const int warp = tid >> 5;
    const int lane = tid & 31;
    const int g    = lane >> 2;             // 0..7
    const int tig  = lane & 3;              // 0..3
    const int qt    = blockIdx.x % QT_TILES;
    const int split = blockIdx.x / QT_TILES;

    const int q0 = qt * 128 + warp * 16 + g;
    const int q1 = q0 + 8;

    // A fragment (row-major 16x16 bf16): rows g/g+8, cols 2tig..2tig+1, +8
    const uint32_t a0 = g_qa[q0 * 8 + tig];
    const uint32_t a1 = g_qa[q1 * 8 + tig];
    const uint32_t a2 = g_qa[q0 * 8 + tig + 4];
    const uint32_t a3 = g_qa[q1 * 8 + tig + 4];

    float se0 = 0.0f, se1 = 0.0f, sw0 = 0.0f, sw1 = 0.0f;

    const int key0 = split * KEYS_PER_SPLIT;
    const float nb = -BIAS;

    for (int tile = 0; tile < TILES; tile++) {
        __syncthreads();
        // stage 512 keys: src float4 f covers key f/2, half f&1 (32B/key)
        {
            const float4* src = reinterpret_cast<const float4*>(g_kb)
                              + (key0 + tile * KEYTILE) * 2;
            float4* dst = reinterpret_cast<float4*>(sk);
            #pragma unroll
            for (int f = tid; f < KEYTILE * 2; f += TPB) {
                int key = f >> 1, half = f & 1;
                dst[key * 3 + half] = src[f];
            }
        }
        __syncthreads();

        for (int jc = 0; jc < (KEYTILE / 8) / 8; jc++) {   // 8 chunks of 8 MMAs
            __half2 se01 = __float2half2_rn(0.0f);
            __half2 se23 = __float2half2_rn(0.0f);
            __half2 sw01 = __float2half2_rn(0.0f);
            __half2 sw23 = __float2half2_rn(0.0f);

            #pragma unroll
            for (int jj = 0; jj < 8; jj++) {
                const int j  = jc * 8 + jj;
                const int kb = j * 8 + g;       // this thread's B-fragment key
                uint32_t b0 = sk[kb * 12 + tig];
                uint32_t b1 = sk[kb * 12 + tig + 4];

                float d0, d1, d2, d3;
                asm volatile(
                    "mma.sync.aligned.m16n8k16.row.col.f32.bf16.bf16.f32 "
                    "{%0,%1,%2,%3}, {%4,%5,%6,%7}, {%8,%9}, {%10,%11,%12,%13};"
                    : "=f"(d0), "=f"(d1), "=f"(d2), "=f"(d3)
                    : "r"(a0), "r"(a1), "r"(a2), "r"(a3), "r"(b0), "r"(b1),
                      "f"(nb), "f"(nb), "f"(nb), "f"(nb));

                // d0,d1: row g; d2,d3: row g+8 (all biased by -BIAS)
                __half2 t01 = __floats2half2_rn(d0, d1);
                __half2 t23 = __floats2half2_rn(d2, d3);
                __half2 e01 = h2exp2(t01);
                __half2 e23 = h2exp2(t23);
                se01 = __hadd2(se01, e01);
                se23 = __hadd2(se23, e23);
                sw01 = __hfma2(e01, t01, sw01);
                sw23 = __hfma2(e23, t23, sw23);
            }

            float2 f;
            f = __half22float2(se01); se0 += f.x + f.y;
            f = __half22float2(sw01); sw0 += f.x + f.y;
            f = __half22float2(se23); se1 += f.x + f.y;
            f = __half22float2(sw23); sw1 += f.x + f.y;
        }
    }

    // reduce across the 4 threads of each row-quad (tids 4g..4g+3)
    se0 += __shfl_xor_sync(0xffffffffu, se0, 1);
    se0 += __shfl_xor_sync(0xffffffffu, se0, 2);
    se1 += __shfl_xor_sync(0xffffffffu, se1, 1);
    se1 += __shfl_xor_sync(0xffffffffu, se1, 2);
    sw0 += __shfl_xor_sync(0xffffffffu, sw0, 1);
    sw0 += __shfl_xor_sync(0xffffffffu, sw0, 2);
    sw1 += __shfl_xor_sync(0xffffffffu, sw1, 1);
    sw1 += __shfl_xor_sync(0xffffffffu, sw1, 2);

    if (tig == 0) {
        g_se[split][q0] = se0;
        g_sw[split][q0] = sw0;
        g_se[split][q1] = se1;
        g_sw[split][q1] = sw1;
    }
}

// ---------------------------------------------------------------------------
// Kernel 2: w = sigmoid(4*ln2 * (sw/se + BIAS)); block-local SOP partial
// M_b = sum_i w_i^2 f_i f_i^T, then the LAST block (atomic counter) reduces
// all partials, L2-normalizes, writes the 256-float output, resets counter.
// (topK=1 -> all points kept; /k cancels in the L2-normalize.)
// ---------------------------------------------------------------------------
__global__ void __launch_bounds__(SOP_BLK) sop_kernel(const float* __restrict__ feats,
                                                      float* __restrict__ out) {
    __shared__ float sf[SOP_BLK][DIM];
    __shared__ float sw2[SOP_BLK];
    __shared__ unsigned int isLast;

    const int tid = threadIdx.x;
    const int b   = blockIdx.x;
    const int p   = b * SOP_BLK + tid;

    float se = 0.0f, sw = 0.0f;
    #pragma unroll
    for (int s = 0; s < KSPLIT; s++) {
        se += g_se[s][p];
        sw += g_sw[s][p];
    }
    const float c4ln2 = 4.0f * 0.6931471805599453f;
    float cf = c4ln2 * (sw / se + BIAS);
    float w = 1.0f / (1.0f + __expf(-cf));
    sw2[tid] = w * w;

    const float4* fp = reinterpret_cast<const float4*>(feats) + p * 4;
    float4 f0 = fp[0], f1 = fp[1], f2 = fp[2], f3 = fp[3];
    sf[tid][0]  = f0.x; sf[tid][1]  = f0.y; sf[tid][2]  = f0.z; sf[tid][3]  = f0.w;
    sf[tid][4]  = f1.x; sf[tid][5]  = f1.y; sf[tid][6]  = f1.z; sf[tid][7]  = f1.w;
    sf[tid][8]  = f2.x; sf[tid][9]  = f2.y; sf[tid][10] = f2.z; sf[tid][11] = f2.w;
    sf[tid][12] = f3.x; sf[tid][13] = f3.y; sf[tid][14] = f3.z; sf[tid][15] = f3.w;
    __syncthreads();

    const int d = tid >> 4;
    const int e = tid & 15;
    float acc = 0.0f;
    #pragma unroll 8
    for (int i = 0; i < SOP_BLK; i++) {
        acc = fmaf(sw2[i] * sf[i][d], sf[i][e], acc);
    }
    g_Mpart[b][tid] = acc;

    // ---- last-block finalize (deterministic; counter self-resets) ----
    __threadfence();
    if (tid == 0) isLast = (atomicAdd(&g_cnt, 1u) == SOP_BLOCKS - 1) ? 1u : 0u;
    __syncthreads();
    if (isLast) {
        __threadfence();
        float v = 0.0f;
        #pragma unroll 8
        for (int bb = 0; bb < SOP_BLOCKS; bb++) v += g_Mpart[bb][tid];

        __syncthreads();          // sw2 reuse safe
        sw2[tid] = v * v;
        __syncthreads();
        #pragma unroll
        for (int o = 128; o > 0; o >>= 1) {
            if (tid < o) sw2[tid] += sw2[tid + o];
            __syncthreads();
        }
        float inv = 1.0f / sqrtf(sw2[0]);
        out[tid] = v * inv;
        if (tid == 0) g_cnt = 0;
    }
}

// ---------------------------------------------------------------------------
extern "C" void kernel_launch(void* const* d_in, const int* in_sizes, int n_in,
                              void* d_out, int out_size) {
    const float* feats = (const float*)d_in[0];
    float* out = (float*)d_out;

    convert_kernel<<<NPTS / 256, 256>>>(feats);
    attn_mma_kernel<<<KSPLIT * QT_TILES, TPB>>>();
    sop_kernel<<<SOP_BLOCKS, SOP_BLK>>>(feats, out);
}

// round 9
// speedup vs baseline: 1.3532x; 1.3532x over previous
#include <cuda_runtime.h>
#include <cuda_bf16.h>
#include <cstdint>

#define NPTS 12288
#define DIM 16
#define KSPLIT 6
#define QT_TILES 96                     // 12288/128 query tiles
#define TPB 256
#define KEYS_PER_SPLIT (NPTS / KSPLIT)  // 2048
#define KEYTILE 512
#define TILES (KEYS_PER_SPLIT / KEYTILE)// 4
#define SOP_BLK 256
#define SOP_BLOCKS (NPTS / SOP_BLK)     // 48

// ---- scratch (__device__ globals; no allocation allowed) ------------------
__device__ uint32_t g_qa[NPTS * 8];         // queries, bf16x2, pre-scaled by 0.25*log2(e)
__device__ uint32_t g_kb[NPTS * 8];         // keys, bf16x2, unscaled
__device__ float g_se[KSPLIT][NPTS];        // exp-sum partials
__device__ float g_sw[KSPLIT][NPTS];        // exp*score-sum partials (log2-units)
__device__ float g_Mpart[SOP_BLOCKS][256];  // per-block SOP partials
__device__ unsigned int g_cnt = 0;          // last-block counter (self-resetting)

__device__ __forceinline__ float ex2_approx(float x) {
    float r; asm("ex2.approx.ftz.f32 %0, %1;" : "=f"(r) : "f"(x)); return r;
}

// ---------------------------------------------------------------------------
// Kernel 0: convert feats (f32) to bf16 row-major arrays.
// One float4 per thread (192 blocks x 256 thr) -> latency-hiding by width.
// g_qa = feats * 0.25*log2(e)  (A operand; MMA output = score in log2 units)
// g_kb = feats                 (B operand)
// ---------------------------------------------------------------------------
__global__ void convert_kernel(const float* __restrict__ feats) {
    const int i = blockIdx.x * 256 + threadIdx.x;   // float4 index, 0..49151
    const float sc = 0.25f * 1.4426950408889634f;
    float4 v = reinterpret_cast<const float4*>(feats)[i];
    __nv_bfloat162 qa0 = __floats2bfloat162_rn(v.x * sc, v.y * sc);
    __nv_bfloat162 qa1 = __floats2bfloat162_rn(v.z * sc, v.w * sc);
    __nv_bfloat162 kb0 = __floats2bfloat162_rn(v.x, v.y);
    __nv_bfloat162 kb1 = __floats2bfloat162_rn(v.z, v.w);
    uint2 qa = make_uint2(*reinterpret_cast<uint32_t*>(&qa0),
                          *reinterpret_cast<uint32_t*>(&qa1));
    uint2 kb = make_uint2(*reinterpret_cast<uint32_t*>(&kb0),
                          *reinterpret_cast<uint32_t*>(&kb1));
    reinterpret_cast<uint2*>(g_qa)[i] = qa;
    reinterpret_cast<uint2*>(g_kb)[i] = kb;
}

// ---------------------------------------------------------------------------
// Kernel 1: tensor-core attention row stats via warp-level mma.sync (R7 path).
// Warp owns 16 queries (A frag, loaded once); loops over 512-key smem tiles
// (48B/key stride -> conflict-free). Per MMA: scores (16q x 8k) in d0..d3;
// epilogue e = 2^t; se += e; sw += e*t (fp32). Quad shfl reduce at end.
// Identity: <ctx_q,f_q> = 4*ln2 * sw/se -> no ctx materialization.
// ---------------------------------------------------------------------------
__global__ void __launch_bounds__(TPB, 4) attn_mma_kernel() {
    __shared__ uint32_t sk[KEYTILE * 12];   // 24 KB, 48B per key (12 words)

    const int tid  = threadIdx.x;
    const int warp = tid >> 5;
    const int lane = tid & 31;
    const int g    = lane >> 2;             // 0..7
    const int tig  = lane & 3;              // 0..3
    const int qt    = blockIdx.x % QT_TILES;
    const int split = blockIdx.x / QT_TILES;

    const int q0 = qt * 128 + warp * 16 + g;
    const int q1 = q0 + 8;

    // A fragment (row-major 16x16 bf16): rows g/g+8, cols 2tig..2tig+1, +8
    const uint32_t a0 = g_qa[q0 * 8 + tig];
    const uint32_t a1 = g_qa[q1 * 8 + tig];
    const uint32_t a2 = g_qa[q0 * 8 + tig + 4];
    const uint32_t a3 = g_qa[q1 * 8 + tig + 4];

    float se0 = 0.0f, se1 = 0.0f, sw0 = 0.0f, sw1 = 0.0f;

    const int key0 = split * KEYS_PER_SPLIT;

    for (int tile = 0; tile < TILES; tile++) {
        __syncthreads();
        // stage 512 keys: src float4 f covers key f/2, half f&1 (32B/key)
        {
            const float4* src = reinterpret_cast<const float4*>(g_kb)
                              + (key0 + tile * KEYTILE) * 2;
            float4* dst = reinterpret_cast<float4*>(sk);
            #pragma unroll
            for (int f = tid; f < KEYTILE * 2; f += TPB) {
                int key = f >> 1, half = f & 1;
                dst[key * 3 + half] = src[f];
            }
        }
        __syncthreads();

        #pragma unroll 4
        for (int j = 0; j < KEYTILE / 8; j++) {
            const int kb = j * 8 + g;       // this thread's B-fragment key
            uint32_t b0 = sk[kb * 12 + tig];
            uint32_t b1 = sk[kb * 12 + tig + 4];

            float d0, d1, d2, d3;
            asm volatile(
                "mma.sync.aligned.m16n8k16.row.col.f32.bf16.bf16.f32 "
                "{%0,%1,%2,%3}, {%4,%5,%6,%7}, {%8,%9}, {%10,%11,%12,%13};"
                : "=f"(d0), "=f"(d1), "=f"(d2), "=f"(d3)
                : "r"(a0), "r"(a1), "r"(a2), "r"(a3), "r"(b0), "r"(b1),
                  "f"(0.0f), "f"(0.0f), "f"(0.0f), "f"(0.0f));

            // d0,d1: row g (keys 2tig,2tig+1); d2,d3: row g+8
            float e;
            e = ex2_approx(d0); se0 += e; sw0 = fmaf(e, d0, sw0);
            e = ex2_approx(d1); se0 += e; sw0 = fmaf(e, d1, sw0);
            e = ex2_approx(d2); se1 += e; sw1 = fmaf(e, d2, sw1);
            e = ex2_approx(d3); se1 += e; sw1 = fmaf(e, d3, sw1);
        }
    }

    // reduce across the 4 threads of each row-quad (tids 4g..4g+3)
    se0 += __shfl_xor_sync(0xffffffffu, se0, 1);
    se0 += __shfl_xor_sync(0xffffffffu, se0, 2);
    se1 += __shfl_xor_sync(0xffffffffu, se1, 1);
    se1 += __shfl_xor_sync(0xffffffffu, se1, 2);
    sw0 += __shfl_xor_sync(0xffffffffu, sw0, 1);
    sw0 += __shfl_xor_sync(0xffffffffu, sw0, 2);
    sw1 += __shfl_xor_sync(0xffffffffu, sw1, 1);
    sw1 += __shfl_xor_sync(0xffffffffu, sw1, 2);

    if (tig == 0) {
        g_se[split][q0] = se0;
        g_sw[split][q0] = sw0;
        g_se[split][q1] = se1;
        g_sw[split][q1] = sw1;
    }
}

// ---------------------------------------------------------------------------
// Kernel 2: w = sigmoid(4*ln2 * sw/se); block-local SOP partial
// M_b = sum_i w_i^2 f_i f_i^T, then the LAST block (atomic counter) reduces
// all partials, L2-normalizes, writes the 256-float output, resets counter.
// (topK=1 -> all points kept; /k cancels in the L2-normalize.)
// ---------------------------------------------------------------------------
__global__ void __launch_bounds__(SOP_BLK) sop_kernel(const float* __restrict__ feats,
                                                      float* __restrict__ out) {
    __shared__ float sf[SOP_BLK][DIM];
    __shared__ float sw2[SOP_BLK];
    __shared__ unsigned int isLast;

    const int tid = threadIdx.x;
    const int b   = blockIdx.x;
    const int p   = b * SOP_BLK + tid;

    float se = 0.0f, sw = 0.0f;
    #pragma unroll
    for (int s = 0; s < KSPLIT; s++) {
        se += g_se[s][p];
        sw += g_sw[s][p];
    }
    const float c4ln2 = 4.0f * 0.6931471805599453f;
    float cf = c4ln2 * sw / se;
    float w = 1.0f / (1.0f + __expf(-cf));
    sw2[tid] = w * w;

    const float4* fp = reinterpret_cast<const float4*>(feats) + p * 4;
    float4 f0 = fp[0], f1 = fp[1], f2 = fp[2], f3 = fp[3];
    sf[tid][0]  = f0.x; sf[tid][1]  = f0.y; sf[tid][2]  = f0.z; sf[tid][3]  = f0.w;
    sf[tid][4]  = f1.x; sf[tid][5]  = f1.y; sf[tid][6]  = f1.z; sf[tid][7]  = f1.w;
    sf[tid][8]  = f2.x; sf[tid][9]  = f2.y; sf[tid][10] = f2.z; sf[tid][11] = f2.w;
    sf[tid][12] = f3.x; sf[tid][13] = f3.y; sf[tid][14] = f3.z; sf[tid][15] = f3.w;
    __syncthreads();

    const int d = tid >> 4;
    const int e = tid & 15;
    float acc = 0.0f;
    #pragma unroll 8
    for (int i = 0; i < SOP_BLK; i++) {
        acc = fmaf(sw2[i] * sf[i][d], sf[i][e], acc);
    }
    g_Mpart[b][tid] = acc;

    // ---- last-block finalize (deterministic; counter self-resets) ----
    __threadfence();
    if (tid == 0) isLast = (atomicAdd(&g_cnt, 1u) == SOP_BLOCKS - 1) ? 1u : 0u;
    __syncthreads();
    if (isLast) {
        __threadfence();
        float v = 0.0f;
        #pragma unroll 8
        for (int bb = 0; bb < SOP_BLOCKS; bb++) v += g_Mpart[bb][tid];

        __syncthreads();          // sw2 reuse safe
        sw2[tid] = v * v;
        __syncthreads();
        #pragma unroll
        for (int o = 128; o > 0; o >>= 1) {
            if (tid < o) sw2[tid] += sw2[tid + o];
            __syncthreads();
        }
        float inv = 1.0f / sqrtf(sw2[0]);
        out[tid] = v * inv;
        if (tid == 0) g_cnt = 0;
    }
}

// ---------------------------------------------------------------------------
extern "C" void kernel_launch(void* const* d_in, const int* in_sizes, int n_in,
                              void* d_out, int out_size) {
    const float* feats = (const float*)d_in[0];
    float* out = (float*)d_out;

    convert_kernel<<<NPTS * 4 / 256, 256>>>(feats);
    attn_mma_kernel<<<KSPLIT * QT_TILES, TPB>>>();
    sop_kernel<<<SOP_BLOCKS, SOP_BLK>>>(feats, out);
}